// round 17
// baseline (speedup 1.0000x reference)
#include <cuda_runtime.h>

// Fixed problem shape: B=8, H=W=512, C=32, n_segments=256
#define B_    8
#define HW_   (512 * 512)
#define C_    32
#define S_    256
#define CPB_  57                  // CTAs per batch
#define NCTA  (B_ * CPB_)         // 456 = 3 x 152 SMs (GB300) -> one exact wave
#define CW    16                  // consumer warps
#define TPB   ((CW + 1) * 32)     // 544: 16 consumer warps + 1 producer warp
#define SEGW  (S_ / CW)           // 16 segments owned per consumer warp
#define BP    64                  // pixels per stage (8 KB image + 256 B ids)
#define UPB   (HW_ / BP)          // 4096 stage-units per batch
#define D     3                   // pipeline depth

#define IMG_BYTES (BP * C_ * 4)   // 8192
#define IDS_BYTES (BP * 4)        // 256
#define TX_BYTES  (IMG_BYTES + IDS_BYTES)

// smem offsets (bytes)
#define OFF_SUM  0                         // [256][32] f32   = 32768
#define OFF_ZC   32768                     // [256][32] u16   = 16384
#define OFF_BUF  49152                     // D * 8192        = 24576
#define OFF_IDS  73728                     // D * 256         =   768
#define OFF_BAR  74496                     // 2*D mbarriers   =    48
#define SMEM_SZ  74560

// Per-CTA partials (.x = sum, .y = count as float; counts << 2^24 -> exact).
// Fully overwritten every launch -> no zeroing, replay-safe, zero atomics.
__device__ float2 g_part[(size_t)NCTA * S_ * C_];   // ~29.9 MB

__device__ __forceinline__ unsigned smem_u32(const void* p) {
    return (unsigned)__cvta_generic_to_shared(p);
}
__device__ __forceinline__ void mbar_init(unsigned a, unsigned cnt) {
    asm volatile("mbarrier.init.shared.b64 [%0], %1;" :: "r"(a), "r"(cnt) : "memory");
}
__device__ __forceinline__ void mbar_expect_tx(unsigned a, unsigned tx) {
    asm volatile("mbarrier.arrive.expect_tx.shared.b64 _, [%0], %1;" :: "r"(a), "r"(tx) : "memory");
}
__device__ __forceinline__ void mbar_arrive(unsigned a) {
    asm volatile("mbarrier.arrive.shared.b64 _, [%0];" :: "r"(a) : "memory");
}
__device__ __forceinline__ void mbar_wait_acq(unsigned a, unsigned ph) {
    asm volatile(
        "{\n\t.reg .pred P;\n\t"
        "WL%=:\n\tmbarrier.try_wait.parity.acquire.cta.shared::cta.b64 P, [%0], %1, 0x989680;\n\t"
        "@P bra WD%=;\n\tbra WL%=;\n\tWD%=:\n\t}"
        :: "r"(a), "r"(ph) : "memory");
}
__device__ __forceinline__ void mbar_wait_rlx(unsigned a, unsigned ph) {
    asm volatile(
        "{\n\t.reg .pred P;\n\t"
        "WL%=:\n\tmbarrier.try_wait.parity.relaxed.cta.shared::cta.b64 P, [%0], %1, 0x989680;\n\t"
        "@P bra WD%=;\n\tbra WL%=;\n\tWD%=:\n\t}"
        :: "r"(a), "r"(ph) : "memory");
}
__device__ __forceinline__ void bulk_g2s(unsigned dst, const void* src,
                                         unsigned bytes, unsigned mbar) {
    asm volatile(
        "cp.async.bulk.shared::cta.global.mbarrier::complete_tx::bytes [%0], [%1], %2, [%3];"
        :: "r"(dst), "l"(src), "r"(bytes), "r"(mbar) : "memory");
}

// Predicated f32 smem add: no branch, no BSSY; predicated-off ops generate
// zero crossbar wavefronts.
__device__ __forceinline__ void sum_add_pred(unsigned addr, float v, int en) {
    asm volatile(
        "{\n\t.reg .pred p;\n\t.reg .f32 t;\n\t"
        "setp.ne.b32 p, %2, 0;\n\t"
        "@p ld.shared.f32 t, [%0];\n\t"
        "@p add.f32 t, t, %1;\n\t"
        "@p st.shared.f32 [%0], t;\n\t}"
        :: "r"(addr), "f"(v), "r"(en) : "memory");
}
// Predicated u16 zero-correction increment: fires only when v == 0.0f
// (essentially never on this data; exact when it does). No branch.
__device__ __forceinline__ void zc_add_pred(unsigned addr, float v) {
    asm volatile(
        "{\n\t.reg .pred p;\n\t.reg .u16 t;\n\t"
        "setp.eq.f32 p, %1, 0F00000000;\n\t"
        "@p ld.shared.u16 t, [%0];\n\t"
        "@p add.u16 t, t, 1;\n\t"
        "@p st.shared.u16 [%0], t;\n\t}"
        :: "r"(addr), "f"(v) : "memory");
}

// ---------------------------------------------------------------------------
// k_accum: warp-specialized mbarrier pipeline (proven R10 scaffold). Producer
// warp streams the image sequentially via cp.async.bulk into a depth-3 stage
// ring; 16 consumer warps accumulate SUMS ONLY into warp-private f32 bins
// (1 LDS.32 + 1 STS.32 per pixel). Per-channel counts are derived:
//   count[seg][ch] = pixel_tally[seg] (register) - zeros[seg][ch] (u16 smem,
//   branchlessly predicated, ~never fires).
// No atomics, no ballots beyond the one ownership ballot, no branches in the
// hot loop. smem 74.6 KB -> 3 CTAs/SM, 456-CTA exact wave, 12 warps/SMSP.
// ---------------------------------------------------------------------------
__global__ void __launch_bounds__(TPB, 3) k_accum(const float* __restrict__ img,
                                                  const int* __restrict__ slic) {
    extern __shared__ char smem[];
    float*          s_sum = (float*)(smem + OFF_SUM);
    unsigned short* s_zc  = (unsigned short*)(smem + OFF_ZC);
    float*          s_buf = (float*)(smem + OFF_BUF);
    int*            s_ids = (int*)(smem + OFF_IDS);
    const unsigned mbase = smem_u32(smem + OFF_BAR);

    const int tid = threadIdx.x, w = tid >> 5, lane = tid & 31;

    #pragma unroll
    for (int i = tid; i < S_ * C_; i += TPB) s_sum[i] = 0.f;
    #pragma unroll
    for (int i = tid; i < S_ * C_ / 2; i += TPB) ((unsigned*)s_zc)[i] = 0u;
    if (tid == 0) {
        #pragma unroll
        for (int i = 0; i < D; i++) {
            mbar_init(mbase + i * 8, 1);            // full: producer expect_tx
            mbar_init(mbase + (D + i) * 8, CW);     // empty: one arrive per consumer warp
        }
    }
    __syncthreads();

    // Per-batch contiguous unit range (71 or 72 units), never straddles batch.
    const int batch = blockIdx.x / CPB_;
    const int c     = blockIdx.x % CPB_;
    const int u0 = batch * UPB + (c * UPB) / CPB_;
    const int nb = batch * UPB + ((c + 1) * UPB) / CPB_ - u0;

    if (w == CW) {
        // ----- producer warp (lane 0 only) -----
        if (lane == 0) {
            int st = 0, ph = 1;                     // phase 1: first D waits pass free
            for (int g = 0; g < nb; g++) {
                mbar_wait_rlx(mbase + (D + st) * 8, (unsigned)ph);
                unsigned fb = mbase + st * 8;
                mbar_expect_tx(fb, TX_BYTES);
                bulk_g2s(smem_u32(s_buf + st * BP * C_),
                         img + (size_t)(u0 + g) * BP * C_, IMG_BYTES, fb);
                bulk_g2s(smem_u32(s_ids + st * BP),
                         slic + (size_t)(u0 + g) * BP, IDS_BYTES, fb);
                if (++st == D) { st = 0; ph ^= 1; }
            }
        }
    } else {
        // ----- consumer warps -----
        const int lo = w * SEGW;
        const unsigned sum_base = smem_u32(s_sum + lo * C_ + lane);
        const unsigned zc_base  = smem_u32(s_zc  + lo * C_ + lane);
        const float* wbuf_ck = s_buf;   // (typing aid)
        (void)wbuf_ck;
        int st = 0, ph = 0;
        int pcnt = 0;                   // lane l (<16): pixel tally for segment lo+l

        for (int g = 0; g < nb; g++) {
            mbar_wait_acq(mbase + st * 8, (unsigned)ph);
            const float* buf0 = s_buf + st * BP * C_;
            const int*   ids  = s_ids + st * BP;

            #pragma unroll
            for (int t = 0; t < 2; t++) {
                const float* buf = buf0 + t * 32 * C_;
                int id = ids[t * 32 + lane] - 1;               // 1-based; 0 -> -1 dropped
                unsigned m = __ballot_sync(0xffffffffu,
                                           ((unsigned)(id - lo)) < (unsigned)SEGW);
                while (m) {
                    int j0 = __ffs(m) - 1; m &= m - 1;
                    int j1 = m ? (__ffs(m) - 1) : -1; if (j1 >= 0) m &= m - 1;
                    int en1 = (j1 >= 0) ? 1 : 0;
                    int s0 = __shfl_sync(0xffffffffu, id, j0) - lo;
                    int s1 = __shfl_sync(0xffffffffu, id, en1 ? j1 : j0) - lo;
                    float v0 = buf[j0 * C_ + lane];
                    float v1 = en1 ? buf[j1 * C_ + lane] : 1.f;   // dummy nonzero
                    // sums: 1 LDS.32 + 1 STS.32 per pixel; same-thread smem
                    // ops are in order -> s0==s1 accumulates correctly.
                    ((float*)0, 0);
                    {
                        // pixel 0: unconditional RMW (plain, no branch)
                        unsigned a0 = sum_base + (unsigned)(s0 * C_) * 4u;
                        asm volatile(
                            "{\n\t.reg .f32 t;\n\t"
                            "ld.shared.f32 t, [%0];\n\t"
                            "add.f32 t, t, %1;\n\t"
                            "st.shared.f32 [%0], t;\n\t}"
                            :: "r"(a0), "f"(v0) : "memory");
                        // pixel 1: predicated RMW (no branch)
                        sum_add_pred(sum_base + (unsigned)(s1 * C_) * 4u, v1, en1);
                    }
                    // pixel tallies in registers (cheap SEL/IADD)
                    pcnt += (lane == s0) ? 1 : 0;
                    pcnt += (en1 && lane == s1) ? 1 : 0;
                    // exact zero correction, branchless predication (~never fires)
                    zc_add_pred(zc_base + (unsigned)(s0 * C_) * 2u, v0);
                    zc_add_pred(zc_base + (unsigned)(s1 * C_) * 2u, v1);
                }
            }
            if (lane == 0) mbar_arrive(mbase + (D + st) * 8);  // release stage
            if (++st == D) { st = 0; ph ^= 1; }
        }

        // Write this warp's partials. count[ch] = pixel_tally - zeros[ch].
        const size_t ob = (size_t)blockIdx.x * S_ * C_;
        #pragma unroll
        for (int sgl = 0; sgl < SEGW; sgl++) {
            float tally = (float)__shfl_sync(0xffffffffu, pcnt, sgl);
            float2 p;
            p.x = s_sum[(lo + sgl) * C_ + lane];
            p.y = tally - (float)s_zc[(lo + sgl) * C_ + lane];
            g_part[ob + (lo + sgl) * C_ + lane] = p;
        }
    }
}

// ---------------------------------------------------------------------------
// k_final: reduce the 57 per-batch CTA partials for each (b, s), divide.
// 8 warps split the chunk list (independent loads -> MLP ~7 per warp),
// smem combine in fixed order -> deterministic. 0/0 -> NaN matches reference.
// ---------------------------------------------------------------------------
__global__ void __launch_bounds__(256) k_final(float* __restrict__ out) {
    __shared__ float2 red[8][32];
    int bs = blockIdx.x, b = bs >> 8, s = bs & (S_ - 1);
    int lane = threadIdx.x & 31, w = threadIdx.x >> 5;

    float2 acc = make_float2(0.f, 0.f);
    for (int k = w; k < CPB_; k += 8) {
        float2 p = g_part[((size_t)(b * CPB_ + k) * S_ + s) * C_ + lane];
        acc.x += p.x; acc.y += p.y;
    }
    red[w][lane] = acc;
    __syncthreads();
    if (w == 0) {
        float sum = 0.f, cnt = 0.f;
        #pragma unroll
        for (int i = 0; i < 8; i++) { sum += red[i][lane].x; cnt += red[i][lane].y; }
        out[((size_t)s * B_ + b) * C_ + lane] = sum / cnt;
    }
}

// ---------------------------------------------------------------------------
// d_in[0] = image_output [8,512,512,32] f32
// d_in[1] = slic_output  [8,512,512,1]  i32
// d_in[2] = n_segments (fixed 256, compiled in)
// d_out   = [256, 8, 32] f32
// ---------------------------------------------------------------------------
extern "C" void kernel_launch(void* const* d_in, const int* in_sizes, int n_in,
                              void* d_out, int out_size) {
    const float* img  = (const float*)d_in[0];
    const int*   slic = (const int*)d_in[1];
    float*       out  = (float*)d_out;

    cudaFuncSetAttribute(k_accum, cudaFuncAttributeMaxDynamicSharedMemorySize, SMEM_SZ);

    k_accum<<<NCTA, TPB, SMEM_SZ>>>(img, slic);
    k_final<<<B_ * S_, 256>>>(out);
}